// round 14
// baseline (speedup 1.0000x reference)
#include <cuda_runtime.h>
#include <math.h>

#define BB 2
#define NN 262144
#define KK 9      // K+1 slots
#define DD 64
#define SS 64
#define BG_BOUND 1.0f
#define SCALE_F 0.125f

// ---------------------------------------------------------------------------
// Folded per-batch operands; computed on device, copied into __constant__.
// Warp-uniform float4 reads -> LDCU.128 on the uniform const port.
// ---------------------------------------------------------------------------
struct __align__(16) PreData {
    float M[BB][KK][DD];   // M = K @ Wq          (logit matrix)
    float P[BB][KK][DD];   // P = slots_full @ out_w^T
    float c[BB][KK];       // c = K @ Wq_b
    float ob[DD];          // out_b
    float ds;              // exp(density_scale)
};
__device__    PreData g_pre;
__constant__  PreData c_pre;

// ---------------------------------------------------------------------------
// Precompute: one block per (batch, slot) pair -> 18 blocks, 64 threads.
// ---------------------------------------------------------------------------
__global__ __launch_bounds__(64)
void precompute(const float* __restrict__ slots,
                const float* __restrict__ empty_slot,
                const float* __restrict__ Wq_w,
                const float* __restrict__ Wq_b,
                const float* __restrict__ Wk_w,
                const float* __restrict__ Wk_b,
                const float* __restrict__ out_w,
                const float* __restrict__ out_b,
                const float* __restrict__ dscale)
{
    __shared__ float sSlot[SS];
    __shared__ float sK[DD];

    const int b = blockIdx.x / KK;
    const int j = blockIdx.x % KK;
    const int d = threadIdx.x;

    sSlot[d] = (j == 0) ? empty_slot[d]
                        : slots[((size_t)b * (KK - 1) + (j - 1)) * SS + d];
    __syncthreads();

    const float4* wk4 = reinterpret_cast<const float4*>(Wk_w  + d * SS);
    const float4* ow4 = reinterpret_cast<const float4*>(out_w + d * SS);
    float kk = Wk_b[d];
    float pp = 0.f;
#pragma unroll
    for (int i = 0; i < SS / 4; i++) {
        const float4 wv = wk4[i];
        const float4 ov = ow4[i];
        const float s0 = sSlot[4 * i], s1 = sSlot[4 * i + 1];
        const float s2 = sSlot[4 * i + 2], s3 = sSlot[4 * i + 3];
        kk = fmaf(s0, wv.x, fmaf(s1, wv.y, fmaf(s2, wv.z, fmaf(s3, wv.w, kk))));
        pp = fmaf(s0, ov.x, fmaf(s1, ov.y, fmaf(s2, ov.z, fmaf(s3, ov.w, pp))));
    }
    sK[d] = kk;
    g_pre.P[b][j][d] = pp;

    if (blockIdx.x == 0) {
        g_pre.ob[d] = out_b[d];
        if (d == 0) g_pre.ds = __expf(dscale[0]);
    }
    __syncthreads();

    float m = 0.f;
#pragma unroll 8
    for (int dd = 0; dd < DD; dd++)
        m = fmaf(sK[dd], Wq_w[dd * DD + d], m);
    g_pre.M[b][j][d] = m;

    if (d == 0) {
        float cc = 0.f;
        for (int dd = 0; dd < DD; dd++)
            cc = fmaf(Wq_b[dd], sK[dd], cc);
        g_pre.c[b][j] = cc;
    }
}

// ---------------------------------------------------------------------------
// Main kernel: 256 threads / 256 points per block.
// Register diet: single l[9] array carries logits -> exp -> normalized w
// in place; density accumulated pre-normalization (sigma = sg * inv).
// __launch_bounds__(256, 5): demand ~50 regs now fits 5 blocks w/o spills.
// ---------------------------------------------------------------------------
__global__ __launch_bounds__(256, 5)
void joint_decoder_main(const float* __restrict__ pf,
                        const float* __restrict__ coor,
                        float* __restrict__ xo,
                        float* __restrict__ wout,
                        float* __restrict__ sig)
{
    __shared__ float4 sT4[4][258];       // conflict-free transpose tile
    __shared__ float  sW[256 * KK];      // staged w for coalesced stores

    const int tid = threadIdx.x;
    const int p0  = blockIdx.x * 256;
    const int b   = blockIdx.x >> 10;    // 1024 blocks per batch
    const int p   = p0 + tid;

    const float4* pf4 = reinterpret_cast<const float4*>(pf + (size_t)p0 * DD);

    // ---- Phase 1: logits via 4 transposed input tiles ----
    float l[KK];                         // acc -> logit -> e -> w (in place)
#pragma unroll
    for (int j = 0; j < KK; j++) l[j] = 0.f;

#pragma unroll
    for (int it = 0; it < 4; it++) {
        if (it) __syncthreads();                 // previous tile fully consumed
#pragma unroll
        for (int r = 0; r < 4; r++) {
            const int q = r * 256 + tid;
            sT4[q & 3][q >> 2] = pf4[(q >> 2) * 16 + it * 4 + (q & 3)];
        }
        __syncthreads();
#pragma unroll
        for (int ii = 0; ii < 4; ii++) {
            const float4 x = sT4[ii][tid];
            const int i4 = (it * 4 + ii) * 4;
#pragma unroll
            for (int j = 0; j < KK; j++) {
                const float4 m = *reinterpret_cast<const float4*>(
                                     &c_pre.M[b][j][i4]);        // LDCU.128
                l[j] = fmaf(x.x, m.x,
                       fmaf(x.y, m.y,
                       fmaf(x.z, m.z,
                       fmaf(x.w, m.w, l[j]))));
            }
        }
    }
    __syncthreads();                             // sT4 free for output phase

#pragma unroll
    for (int j = 0; j < KK; j++)
        l[j] = (l[j] + c_pre.c[b][j]) * SCALE_F;

    // ---- force_bg mask: direct scalar LDG ----
    const float* cp = coor + (size_t)p * 3;
    const float c0 = cp[0], c1 = cp[1], c2 = cp[2];
    const bool inb = (fabsf(c0) <= BG_BOUND) && (fabsf(c1) <= BG_BOUND) &&
                     (fabsf(c2) <= BG_BOUND);

    // ---- masked softmax + density, single array in place ----
    float mx = fmaxf(l[0], l[1]);
    if (inb) {
#pragma unroll
        for (int j = 2; j < KK; j++) mx = fmaxf(mx, l[j]);
    }
    float s, sg = 0.f;
    {
        const float e0 = __expf(l[0] - mx);
        l[0] = e0; s = e0;
    }
#pragma unroll
    for (int j = 1; j < KK; j++) {
        const float e = (j < 2 || inb) ? __expf(l[j] - mx) : 0.f;
        sg = fmaf(fmaxf(l[j], 0.f), e, sg);      // pre-normalization density
        l[j] = e; s += e;
    }
    const float inv = __frcp_rn(s);
#pragma unroll
    for (int j = 0; j < KK; j++) l[j] *= inv;    // l[] now holds w[]
    sig[p] = sg * inv * c_pre.ds;

#pragma unroll
    for (int j = 0; j < KK; j++) sW[tid * KK + j] = l[j];   // stride 9: no conflicts

    // ---- Phase 2: xo via 4 transposed output tiles ----
    float4* xo4 = reinterpret_cast<float4*>(xo + (size_t)p0 * DD);
#pragma unroll
    for (int it = 0; it < 4; it++) {
        if (it) __syncthreads();                 // previous tile fully drained
#pragma unroll
        for (int ii = 0; ii < 4; ii++) {
            const int i4 = (it * 4 + ii) * 4;
            float4 o = *reinterpret_cast<const float4*>(&c_pre.ob[i4]); // LDCU.128
#pragma unroll
            for (int j = 0; j < KK; j++) {
                const float4 q = *reinterpret_cast<const float4*>(
                                     &c_pre.P[b][j][i4]);        // LDCU.128
                o.x = fmaf(l[j], q.x, o.x);
                o.y = fmaf(l[j], q.y, o.y);
                o.z = fmaf(l[j], q.z, o.z);
                o.w = fmaf(l[j], q.w, o.w);
            }
            sT4[ii][tid] = o;
        }
        __syncthreads();
#pragma unroll
        for (int r = 0; r < 4; r++) {
            const int q = r * 256 + tid;
            xo4[(q >> 2) * 16 + it * 4 + (q & 3)] = sT4[q & 3][q >> 2];
        }
    }

    // ---- w out: float4-coalesced copy (ordered by the phase-2 barriers) ----
    {
        const float4* sw4 = reinterpret_cast<const float4*>(sW);
        float4* wg4 = reinterpret_cast<float4*>(wout + (size_t)p0 * KK);
        wg4[tid]       = sw4[tid];
        wg4[tid + 256] = sw4[tid + 256];
        if (tid < 64) wg4[tid + 512] = sw4[tid + 512];
    }
}

// ---------------------------------------------------------------------------
// Launch
// ---------------------------------------------------------------------------
extern "C" void kernel_launch(void* const* d_in, const int* in_sizes, int n_in,
                              void* d_out, int out_size)
{
    const float* pf     = (const float*)d_in[0];   // point_feats [B,N,D]
    const float* slots  = (const float*)d_in[2];   // [B,K,S]
    const float* coor   = (const float*)d_in[3];   // [B,N,3]
    const float* empty  = (const float*)d_in[4];   // [1,1,S]
    const float* Wq_w   = (const float*)d_in[5];
    const float* Wq_b   = (const float*)d_in[6];
    const float* Wk_w   = (const float*)d_in[7];
    const float* Wk_b   = (const float*)d_in[8];
    const float* out_w  = (const float*)d_in[9];
    const float* out_b  = (const float*)d_in[10];
    const float* dscale = (const float*)d_in[11];

    float* out  = (float*)d_out;
    float* xo   = out;                              // [B,N,64]
    float* wout = out + (size_t)BB * NN * DD;       // [B,N,9]
    float* sig  = wout + (size_t)BB * NN * KK;      // [B,N]

    precompute<<<BB * KK, 64>>>(slots, empty, Wq_w, Wq_b, Wk_w, Wk_b,
                                out_w, out_b, dscale);

    void* g_pre_addr = nullptr;
    cudaGetSymbolAddress(&g_pre_addr, g_pre);
    cudaMemcpyToSymbolAsync(c_pre, g_pre_addr, sizeof(PreData), 0,
                            cudaMemcpyDeviceToDevice);

    joint_decoder_main<<<(BB * NN) / 256, 256>>>(pf, coor, xo, wout, sig);
}

// round 15
// speedup vs baseline: 1.8449x; 1.8449x over previous
#include <cuda_runtime.h>
#include <math.h>

#define BB 2
#define NN 262144
#define KK 9      // K+1 slots
#define DD 64
#define SS 64
#define BG_BOUND 1.0f
#define SCALE_F 0.125f

// ---------------------------------------------------------------------------
// Folded per-batch operands; computed on device, copied into __constant__.
// Warp-uniform float4 reads -> LDCU.128 on the uniform const port.
// ---------------------------------------------------------------------------
struct __align__(16) PreData {
    float M[BB][KK][DD];   // M = K @ Wq          (logit matrix)
    float P[BB][KK][DD];   // P = slots_full @ out_w^T
    float c[BB][KK];       // c = K @ Wq_b
    float ob[DD];          // out_b
    float ds;              // exp(density_scale)
};
__device__    PreData g_pre;
__constant__  PreData c_pre;

// ---------------------------------------------------------------------------
// Precompute: one block per (batch, slot) pair -> 18 blocks, 64 threads.
// ---------------------------------------------------------------------------
__global__ __launch_bounds__(64)
void precompute(const float* __restrict__ slots,
                const float* __restrict__ empty_slot,
                const float* __restrict__ Wq_w,
                const float* __restrict__ Wq_b,
                const float* __restrict__ Wk_w,
                const float* __restrict__ Wk_b,
                const float* __restrict__ out_w,
                const float* __restrict__ out_b,
                const float* __restrict__ dscale)
{
    __shared__ float sSlot[SS];
    __shared__ float sK[DD];

    const int b = blockIdx.x / KK;
    const int j = blockIdx.x % KK;
    const int d = threadIdx.x;

    sSlot[d] = (j == 0) ? empty_slot[d]
                        : slots[((size_t)b * (KK - 1) + (j - 1)) * SS + d];
    __syncthreads();

    const float4* wk4 = reinterpret_cast<const float4*>(Wk_w  + d * SS);
    const float4* ow4 = reinterpret_cast<const float4*>(out_w + d * SS);
    float kk = Wk_b[d];
    float pp = 0.f;
#pragma unroll
    for (int i = 0; i < SS / 4; i++) {
        const float4 wv = wk4[i];
        const float4 ov = ow4[i];
        const float s0 = sSlot[4 * i], s1 = sSlot[4 * i + 1];
        const float s2 = sSlot[4 * i + 2], s3 = sSlot[4 * i + 3];
        kk = fmaf(s0, wv.x, fmaf(s1, wv.y, fmaf(s2, wv.z, fmaf(s3, wv.w, kk))));
        pp = fmaf(s0, ov.x, fmaf(s1, ov.y, fmaf(s2, ov.z, fmaf(s3, ov.w, pp))));
    }
    sK[d] = kk;
    g_pre.P[b][j][d] = pp;

    if (blockIdx.x == 0) {
        g_pre.ob[d] = out_b[d];
        if (d == 0) g_pre.ds = __expf(dscale[0]);
    }
    __syncthreads();

    float m = 0.f;
#pragma unroll 8
    for (int dd = 0; dd < DD; dd++)
        m = fmaf(sK[dd], Wq_w[dd * DD + d], m);
    g_pre.M[b][j][d] = m;

    if (d == 0) {
        float cc = 0.f;
        for (int dd = 0; dd < DD; dd++)
            cc = fmaf(Wq_b[dd], sK[dd], cc);
        g_pre.c[b][j] = cc;
    }
}

// ---------------------------------------------------------------------------
// Main kernel: 256 threads / 256 points per block.
// Input staging via cp.async.cg (global->shared, no register transit),
// double-buffered so copy(it+1) overlaps compute(it). Register demand drops
// below the (256,5) cap -> 5 blocks/SM without spills.
// ---------------------------------------------------------------------------
__global__ __launch_bounds__(256, 5)
void joint_decoder_main(const float* __restrict__ pf,
                        const float* __restrict__ coor,
                        float* __restrict__ xo,
                        float* __restrict__ wout,
                        float* __restrict__ sig)
{
    __shared__ float4 sT4[2][4][258];    // two conflict-free transpose tiles
    __shared__ float  sW[256 * KK];      // staged w for coalesced stores

    const int tid = threadIdx.x;
    const int p0  = blockIdx.x * 256;
    const int b   = blockIdx.x >> 10;    // 1024 blocks per batch
    const int p   = p0 + tid;

    const float4* pf4 = reinterpret_cast<const float4*>(pf + (size_t)p0 * DD);
    const unsigned sbase =
        (unsigned)__cvta_generic_to_shared(&sT4[0][0][0]);

    // ---- Phase 1: logits via 4 cp.async double-buffered tiles ----
    float l[KK];                         // acc -> logit -> e -> w (in place)
#pragma unroll
    for (int j = 0; j < KK; j++) l[j] = 0.f;

    // prologue: stage tile 0 into buf 0
#pragma unroll
    for (int r = 0; r < 4; r++) {
        const int q = r * 256 + tid;
        const unsigned dst = sbase + (unsigned)(((q & 3) * 258 + (q >> 2)) * 16);
        const float4* src = pf4 + (size_t)(q >> 2) * 16 + (q & 3);
        asm volatile("cp.async.cg.shared.global [%0], [%1], 16;"
                     :: "r"(dst), "l"(src));
    }
    asm volatile("cp.async.commit_group;" ::: "memory");

#pragma unroll
    for (int it = 0; it < 4; it++) {
        asm volatile("cp.async.wait_group 0;" ::: "memory");
        __syncthreads();                 // tile it visible to all threads
        if (it < 3) {                    // stage tile it+1 into other buffer
            const unsigned bufo = (unsigned)(((it + 1) & 1) * 4 * 258 * 16);
#pragma unroll
            for (int r = 0; r < 4; r++) {
                const int q = r * 256 + tid;
                const unsigned dst =
                    sbase + bufo + (unsigned)(((q & 3) * 258 + (q >> 2)) * 16);
                const float4* src =
                    pf4 + (size_t)(q >> 2) * 16 + (it + 1) * 4 + (q & 3);
                asm volatile("cp.async.cg.shared.global [%0], [%1], 16;"
                             :: "r"(dst), "l"(src));
            }
            asm volatile("cp.async.commit_group;" ::: "memory");
        }
        const int buf = it & 1;
#pragma unroll
        for (int ii = 0; ii < 4; ii++) {
            const float4 x = sT4[buf][ii][tid];
            const int i4 = (it * 4 + ii) * 4;
#pragma unroll
            for (int j = 0; j < KK; j++) {
                const float4 m = *reinterpret_cast<const float4*>(
                                     &c_pre.M[b][j][i4]);        // LDCU.128
                l[j] = fmaf(x.x, m.x,
                       fmaf(x.y, m.y,
                       fmaf(x.z, m.z,
                       fmaf(x.w, m.w, l[j]))));
            }
        }
    }

#pragma unroll
    for (int j = 0; j < KK; j++)
        l[j] = (l[j] + c_pre.c[b][j]) * SCALE_F;

    // ---- force_bg mask: direct scalar LDG ----
    const float* cp = coor + (size_t)p * 3;
    const float c0 = cp[0], c1 = cp[1], c2 = cp[2];
    const bool inb = (fabsf(c0) <= BG_BOUND) && (fabsf(c1) <= BG_BOUND) &&
                     (fabsf(c2) <= BG_BOUND);

    // ---- masked softmax + density, single array in place ----
    float mx = fmaxf(l[0], l[1]);
    if (inb) {
#pragma unroll
        for (int j = 2; j < KK; j++) mx = fmaxf(mx, l[j]);
    }
    float s, sg = 0.f;
    {
        const float e0 = __expf(l[0] - mx);
        l[0] = e0; s = e0;
    }
#pragma unroll
    for (int j = 1; j < KK; j++) {
        const float e = (j < 2 || inb) ? __expf(l[j] - mx) : 0.f;
        sg = fmaf(fmaxf(l[j], 0.f), e, sg);      // pre-normalization density
        l[j] = e; s += e;
    }
    const float inv = __frcp_rn(s);
#pragma unroll
    for (int j = 0; j < KK; j++) l[j] *= inv;    // l[] now holds w[]
    sig[p] = sg * inv * c_pre.ds;

#pragma unroll
    for (int j = 0; j < KK; j++) sW[tid * KK + j] = l[j];   // stride 9: no conflicts

    // ---- Phase 2: xo via 4 transposed output tiles (alternating buffers) ----
    // Safety: STS(it) into buf it&1; previous reader of that buffer finished
    // before the preceding barrier (phase-1 consumes / copy-out it-2).
    float4* xo4 = reinterpret_cast<float4*>(xo + (size_t)p0 * DD);
#pragma unroll
    for (int it = 0; it < 4; it++) {
        const int buf = it & 1;
#pragma unroll
        for (int ii = 0; ii < 4; ii++) {
            const int i4 = (it * 4 + ii) * 4;
            float4 o = *reinterpret_cast<const float4*>(&c_pre.ob[i4]); // LDCU.128
#pragma unroll
            for (int j = 0; j < KK; j++) {
                const float4 q = *reinterpret_cast<const float4*>(
                                     &c_pre.P[b][j][i4]);        // LDCU.128
                o.x = fmaf(l[j], q.x, o.x);
                o.y = fmaf(l[j], q.y, o.y);
                o.z = fmaf(l[j], q.z, o.z);
                o.w = fmaf(l[j], q.w, o.w);
            }
            sT4[buf][ii][tid] = o;
        }
        __syncthreads();
#pragma unroll
        for (int r = 0; r < 4; r++) {
            const int q = r * 256 + tid;
            xo4[(q >> 2) * 16 + it * 4 + (q & 3)] = sT4[buf][q & 3][q >> 2];
        }
    }

    // ---- w out: float4-coalesced copy (sW ordered by the phase-2 barriers) ----
    {
        const float4* sw4 = reinterpret_cast<const float4*>(sW);
        float4* wg4 = reinterpret_cast<float4*>(wout + (size_t)p0 * KK);
        wg4[tid]       = sw4[tid];
        wg4[tid + 256] = sw4[tid + 256];
        if (tid < 64) wg4[tid + 512] = sw4[tid + 512];
    }
}

// ---------------------------------------------------------------------------
// Launch
// ---------------------------------------------------------------------------
extern "C" void kernel_launch(void* const* d_in, const int* in_sizes, int n_in,
                              void* d_out, int out_size)
{
    const float* pf     = (const float*)d_in[0];   // point_feats [B,N,D]
    const float* slots  = (const float*)d_in[2];   // [B,K,S]
    const float* coor   = (const float*)d_in[3];   // [B,N,3]
    const float* empty  = (const float*)d_in[4];   // [1,1,S]
    const float* Wq_w   = (const float*)d_in[5];
    const float* Wq_b   = (const float*)d_in[6];
    const float* Wk_w   = (const float*)d_in[7];
    const float* Wk_b   = (const float*)d_in[8];
    const float* out_w  = (const float*)d_in[9];
    const float* out_b  = (const float*)d_in[10];
    const float* dscale = (const float*)d_in[11];

    float* out  = (float*)d_out;
    float* xo   = out;                              // [B,N,64]
    float* wout = out + (size_t)BB * NN * DD;       // [B,N,9]
    float* sig  = wout + (size_t)BB * NN * KK;      // [B,N]

    precompute<<<BB * KK, 64>>>(slots, empty, Wq_w, Wq_b, Wk_w, Wk_b,
                                out_w, out_b, dscale);

    void* g_pre_addr = nullptr;
    cudaGetSymbolAddress(&g_pre_addr, g_pre);
    cudaMemcpyToSymbolAsync(c_pre, g_pre_addr, sizeof(PreData), 0,
                            cudaMemcpyDeviceToDevice);

    joint_decoder_main<<<(BB * NN) / 256, 256>>>(pf, coor, xo, wout, sig);
}

// round 16
// speedup vs baseline: 2.1111x; 1.1443x over previous
#include <cuda_runtime.h>
#include <math.h>

#define BB 2
#define NN 262144
#define KK 9      // K+1 slots
#define DD 64
#define SS 64
#define PTS 128   // points per block
#define BG_BOUND 1.0f
#define SCALE_F 0.125f

// ---------------------------------------------------------------------------
// Folded per-batch operands; computed on device, copied into __constant__.
// Warp-uniform float4 reads -> LDCU.128 on the uniform const port.
// ---------------------------------------------------------------------------
struct __align__(16) PreData {
    float M[BB][KK][DD];   // M = K @ Wq          (logit matrix)
    float P[BB][KK][DD];   // P = slots_full @ out_w^T
    float c[BB][KK];       // c = K @ Wq_b
    float ob[DD];          // out_b
    float ds;              // exp(density_scale)
};
__device__    PreData g_pre;
__constant__  PreData c_pre;

// ---------------------------------------------------------------------------
// Precompute: one block per (batch, slot) pair -> 18 blocks, 64 threads.
// ---------------------------------------------------------------------------
__global__ __launch_bounds__(64)
void precompute(const float* __restrict__ slots,
                const float* __restrict__ empty_slot,
                const float* __restrict__ Wq_w,
                const float* __restrict__ Wq_b,
                const float* __restrict__ Wk_w,
                const float* __restrict__ Wk_b,
                const float* __restrict__ out_w,
                const float* __restrict__ out_b,
                const float* __restrict__ dscale)
{
    __shared__ float sSlot[SS];
    __shared__ float sK[DD];

    const int b = blockIdx.x / KK;
    const int j = blockIdx.x % KK;
    const int d = threadIdx.x;

    sSlot[d] = (j == 0) ? empty_slot[d]
                        : slots[((size_t)b * (KK - 1) + (j - 1)) * SS + d];
    __syncthreads();

    const float4* wk4 = reinterpret_cast<const float4*>(Wk_w  + d * SS);
    const float4* ow4 = reinterpret_cast<const float4*>(out_w + d * SS);
    float kk = Wk_b[d];
    float pp = 0.f;
#pragma unroll
    for (int i = 0; i < SS / 4; i++) {
        const float4 wv = wk4[i];
        const float4 ov = ow4[i];
        const float s0 = sSlot[4 * i], s1 = sSlot[4 * i + 1];
        const float s2 = sSlot[4 * i + 2], s3 = sSlot[4 * i + 3];
        kk = fmaf(s0, wv.x, fmaf(s1, wv.y, fmaf(s2, wv.z, fmaf(s3, wv.w, kk))));
        pp = fmaf(s0, ov.x, fmaf(s1, ov.y, fmaf(s2, ov.z, fmaf(s3, ov.w, pp))));
    }
    sK[d] = kk;
    g_pre.P[b][j][d] = pp;

    if (blockIdx.x == 0) {
        g_pre.ob[d] = out_b[d];
        if (d == 0) g_pre.ds = __expf(dscale[0]);
    }
    __syncthreads();

    float m = 0.f;
#pragma unroll 8
    for (int dd = 0; dd < DD; dd++)
        m = fmaf(sK[dd], Wq_w[dd * DD + d], m);
    g_pre.M[b][j][d] = m;

    if (d == 0) {
        float cc = 0.f;
        for (int dd = 0; dd < DD; dd++)
            cc = fmaf(Wq_b[dd], sK[dd], cc);
        g_pre.c[b][j] = cc;
    }
}

// ---------------------------------------------------------------------------
// Main kernel: 128 threads / 128 points per block (4096 blocks).
// Smaller blocks -> 8 independent barrier domains per SM; per-block tile
// order rotated by blockIdx so co-resident blocks touch different tiles at
// different times (decorrelates L1/DRAM bursts). Conflict-free tile [4][130]
// (plane stride == 2 mod 8). Constants via LDCU.128.
// ---------------------------------------------------------------------------
__global__ __launch_bounds__(128)
void joint_decoder_main(const float* __restrict__ pf,
                        const float* __restrict__ coor,
                        float* __restrict__ xo,
                        float* __restrict__ wout,
                        float* __restrict__ sig)
{
    __shared__ float4 sT4[4][130];       // conflict-free transpose tile
    __shared__ float  sW[PTS * KK];      // staged w for coalesced stores

    const int tid = threadIdx.x;
    const int bid = blockIdx.x;
    const int p0  = bid * PTS;
    const int b   = bid >> 11;           // 2048 blocks per batch
    const int p   = p0 + tid;

    const float4* pf4 = reinterpret_cast<const float4*>(pf + (size_t)p0 * DD);

    // ---- Phase 1: logits via 4 transposed input tiles (rotated order) ----
    float l[KK];                         // acc -> logit -> e -> w (in place)
#pragma unroll
    for (int j = 0; j < KK; j++) l[j] = 0.f;

#pragma unroll
    for (int it = 0; it < 4; it++) {
        const int itr = (it + bid) & 3;          // per-block tile rotation
        if (it) __syncthreads();                 // previous tile fully consumed
#pragma unroll
        for (int r = 0; r < 4; r++) {
            const int q = r * 128 + tid;
            sT4[q & 3][q >> 2] = pf4[(q >> 2) * 16 + itr * 4 + (q & 3)];
        }
        __syncthreads();
#pragma unroll
        for (int ii = 0; ii < 4; ii++) {
            const float4 x = sT4[ii][tid];
            const int i4 = (itr * 4 + ii) * 4;
#pragma unroll
            for (int j = 0; j < KK; j++) {
                const float4 m = *reinterpret_cast<const float4*>(
                                     &c_pre.M[b][j][i4]);        // LDCU.128
                l[j] = fmaf(x.x, m.x,
                       fmaf(x.y, m.y,
                       fmaf(x.z, m.z,
                       fmaf(x.w, m.w, l[j]))));
            }
        }
    }
    __syncthreads();                             // sT4 free for output phase

#pragma unroll
    for (int j = 0; j < KK; j++)
        l[j] = (l[j] + c_pre.c[b][j]) * SCALE_F;

    // ---- force_bg mask: direct scalar LDG ----
    const float* cp = coor + (size_t)p * 3;
    const float c0 = cp[0], c1 = cp[1], c2 = cp[2];
    const bool inb = (fabsf(c0) <= BG_BOUND) && (fabsf(c1) <= BG_BOUND) &&
                     (fabsf(c2) <= BG_BOUND);

    // ---- masked softmax + density, single array in place ----
    float mx = fmaxf(l[0], l[1]);
    if (inb) {
#pragma unroll
        for (int j = 2; j < KK; j++) mx = fmaxf(mx, l[j]);
    }
    float s, sg = 0.f;
    {
        const float e0 = __expf(l[0] - mx);
        l[0] = e0; s = e0;
    }
#pragma unroll
    for (int j = 1; j < KK; j++) {
        const float e = (j < 2 || inb) ? __expf(l[j] - mx) : 0.f;
        sg = fmaf(fmaxf(l[j], 0.f), e, sg);      // pre-normalization density
        l[j] = e; s += e;
    }
    const float inv = __frcp_rn(s);
#pragma unroll
    for (int j = 0; j < KK; j++) l[j] *= inv;    // l[] now holds w[]
    sig[p] = sg * inv * c_pre.ds;

#pragma unroll
    for (int j = 0; j < KK; j++) sW[tid * KK + j] = l[j];   // stride 9: no conflicts

    // ---- Phase 2: xo via 4 transposed output tiles (rotated order) ----
    float4* xo4 = reinterpret_cast<float4*>(xo + (size_t)p0 * DD);
#pragma unroll
    for (int it = 0; it < 4; it++) {
        const int itr = (it + bid) & 3;
        if (it) __syncthreads();                 // previous tile fully drained
#pragma unroll
        for (int ii = 0; ii < 4; ii++) {
            const int i4 = (itr * 4 + ii) * 4;
            float4 o = *reinterpret_cast<const float4*>(&c_pre.ob[i4]); // LDCU.128
#pragma unroll
            for (int j = 0; j < KK; j++) {
                const float4 q = *reinterpret_cast<const float4*>(
                                     &c_pre.P[b][j][i4]);        // LDCU.128
                o.x = fmaf(l[j], q.x, o.x);
                o.y = fmaf(l[j], q.y, o.y);
                o.z = fmaf(l[j], q.z, o.z);
                o.w = fmaf(l[j], q.w, o.w);
            }
            sT4[ii][tid] = o;
        }
        __syncthreads();
#pragma unroll
        for (int r = 0; r < 4; r++) {
            const int q = r * 128 + tid;
            xo4[(q >> 2) * 16 + itr * 4 + (q & 3)] = sT4[q & 3][q >> 2];
        }
    }

    // ---- w out: float4-coalesced copy (ordered by the phase-2 barriers) ----
    {
        const float4* sw4 = reinterpret_cast<const float4*>(sW);
        float4* wg4 = reinterpret_cast<float4*>(wout + (size_t)p0 * KK);
        wg4[tid]       = sw4[tid];
        wg4[tid + 128] = sw4[tid + 128];
        if (tid < 32) wg4[tid + 256] = sw4[tid + 256];
    }
}

// ---------------------------------------------------------------------------
// Launch
// ---------------------------------------------------------------------------
extern "C" void kernel_launch(void* const* d_in, const int* in_sizes, int n_in,
                              void* d_out, int out_size)
{
    const float* pf     = (const float*)d_in[0];   // point_feats [B,N,D]
    const float* slots  = (const float*)d_in[2];   // [B,K,S]
    const float* coor   = (const float*)d_in[3];   // [B,N,3]
    const float* empty  = (const float*)d_in[4];   // [1,1,S]
    const float* Wq_w   = (const float*)d_in[5];
    const float* Wq_b   = (const float*)d_in[6];
    const float* Wk_w   = (const float*)d_in[7];
    const float* Wk_b   = (const float*)d_in[8];
    const float* out_w  = (const float*)d_in[9];
    const float* out_b  = (const float*)d_in[10];
    const float* dscale = (const float*)d_in[11];

    float* out  = (float*)d_out;
    float* xo   = out;                              // [B,N,64]
    float* wout = out + (size_t)BB * NN * DD;       // [B,N,9]
    float* sig  = wout + (size_t)BB * NN * KK;      // [B,N]

    precompute<<<BB * KK, 64>>>(slots, empty, Wq_w, Wq_b, Wk_w, Wk_b,
                                out_w, out_b, dscale);

    void* g_pre_addr = nullptr;
    cudaGetSymbolAddress(&g_pre_addr, g_pre);
    cudaMemcpyToSymbolAsync(c_pre, g_pre_addr, sizeof(PreData), 0,
                            cudaMemcpyDeviceToDevice);

    joint_decoder_main<<<(BB * NN) / PTS, 128>>>(pf, coor, xo, wout, sig);
}